// round 16
// baseline (speedup 1.0000x reference)
#include <cuda_runtime.h>
#include <cuda_fp16.h>
#include <math.h>
#include <stdint.h>

#define N_NODES 20000
#define F_DIM   256
#define HID     128
#define OUTC    7
#define E_EDGES 320000
#define SB      157      // stats blocks, 128 rows each
#define BKT     64       // neighbor bucket capacity per node

// ---------------- scratch ----------------
__device__ float   g_stat[SB][2][F_DIM];
__device__ float   g_mean[F_DIM];
__device__ float   g_rstd[F_DIM];
__device__ int     g_meta[2 * N_NODES + 1];      // [0,N) deg | [N,2N) cur | [2N] done-counter
__device__ int     g_csrc[N_NODES * BKT];        // bucketed in-neighbors
__device__ float   g_c0p[64][2][HID];
__device__ float   g_c0[HID];
__device__ __half2 g_g1h[(size_t)N_NODES * 64];  // linear1 out (+c0), PRE-SCALED by dinv, fp16
__device__ float   g_g2[N_NODES * 8];            // linear2 out, PRE-SCALED by dinv

#define DEG(i)  g_meta[i]
#define CUR(i)  g_meta[N_NODES + (i)]

__device__ __forceinline__ uint32_t f2tf(float f) {
    uint32_t r; asm("cvt.rna.tf32.f32 %0, %1;" : "=r"(r) : "f"(f)); return r;
}
__device__ __forceinline__ void mma8(float* c, uint32_t a0, uint32_t a1, uint32_t a2,
                                     uint32_t a3, uint32_t b0, uint32_t b1) {
    asm volatile(
        "mma.sync.aligned.m16n8k8.row.col.f32.tf32.tf32.f32 "
        "{%0,%1,%2,%3},{%4,%5,%6,%7},{%8,%9},{%0,%1,%2,%3};"
        : "+f"(c[0]), "+f"(c[1]), "+f"(c[2]), "+f"(c[3])
        : "r"(a0), "r"(a1), "r"(a2), "r"(a3), "r"(b0), "r"(b1));
}

// ===== K_A: stats (157) | c0 partials (64) | count (157) | scatter (313) =====
// deg/cur/done pre-zeroed by one memset. Last-arriving block finalizes mean/rstd + c0.
__global__ void __launch_bounds__(256) kA(const float* __restrict__ x,
                                          const float* __restrict__ emb,
                                          const float* __restrict__ W1,
                                          const int* __restrict__ ei) {
    int b = blockIdx.x, t = threadIdx.x;
    if (b < SB) {
        int r0 = b * 128;
        float s = 0.f, q = 0.f;
        for (int r = 0; r < 128; ++r) {
            int rr = r0 + r;
            if (rr < N_NODES) {
                float v = x[(size_t)rr * F_DIM + t];
                s += v; q += v * v;
            }
        }
        g_stat[b][0][t] = s;
        g_stat[b][1][t] = q;
    } else if (b < SB + 64) {
        __shared__ float se[252];
        int cb = b - SB;
        int f0 = cb * 4;
        for (int i = t; i < 252; i += 256) se[i] = emb[f0 * 63 + i];
        __syncthreads();
        int h = t & 127, fp = t >> 7;
        float acc = 0.f;
        #pragma unroll
        for (int q2 = 0; q2 < 2; ++q2) {
            int f = f0 + fp * 2 + q2;
            const float* wrow = W1 + (size_t)f * 64 * HID + h;
            const float* ee = se + (fp * 2 + q2) * 63;
            #pragma unroll 7
            for (int j = 0; j < 63; ++j) acc += ee[j] * wrow[(size_t)j * HID];
        }
        g_c0p[cb][fp][h] = acc;
    } else if (b < SB + 64 + 157) {
        int base = ((b - SB - 64) * 256 + t) * 8;
        if (base < E_EDGES) {
            const int4* p = (const int4*)(ei + E_EDGES + base);
            int4 d0 = p[0], d1 = p[1];
            atomicAdd(&DEG(d0.x), 1); atomicAdd(&DEG(d0.y), 1);
            atomicAdd(&DEG(d0.z), 1); atomicAdd(&DEG(d0.w), 1);
            atomicAdd(&DEG(d1.x), 1); atomicAdd(&DEG(d1.y), 1);
            atomicAdd(&DEG(d1.z), 1); atomicAdd(&DEG(d1.w), 1);
        }
    } else {
        int base = ((b - SB - 64 - 157) * 256 + t) * 4;
        if (base < E_EDGES) {
            int4 s4 = *(const int4*)(ei + base);
            int4 d4 = *(const int4*)(ei + E_EDGES + base);
            int s[4] = {s4.x, s4.y, s4.z, s4.w};
            int d[4] = {d4.x, d4.y, d4.z, d4.w};
            int p[4];
            #pragma unroll
            for (int i = 0; i < 4; ++i) p[i] = atomicAdd(&CUR(d[i]), 1);
            #pragma unroll
            for (int i = 0; i < 4; ++i)
                if (p[i] < BKT) g_csrc[d[i] * BKT + p[i]] = s[i];
        }
    }

    // ---- last-block finalize of mean/rstd + c0 ----
    __shared__ int sLast;
    __threadfence();
    __syncthreads();
    if (t == 0)
        sLast = (atomicAdd(&g_meta[2 * N_NODES], 1) == (int)gridDim.x - 1);
    __syncthreads();
    if (sLast) {
        float s = 0.f, q = 0.f;
        for (int i = 0; i < SB; ++i) { s += g_stat[i][0][t]; q += g_stat[i][1][t]; }
        float m = s / N_NODES;
        float var = fmaxf(q / N_NODES - m * m, 0.f);
        float sd = sqrtf(var);
        if (sd == 0.f) sd = 1.f;
        g_mean[t] = m; g_rstd[t] = 1.f / sd;
        if (t < HID) {
            float c = 0.f;
            for (int i = 0; i < 64; ++i) c += g_c0p[i][0][t] + g_c0p[i][1][t];
            g_c0[t] = c;
        }
    }
}

// ===== K_C: tf32 gemm1, 128-row tiles, fp16 dinv-scaled epilogue (dinv on the fly) =====
__global__ void __launch_bounds__(256, 2) kC(const float* __restrict__ x,
                                             const float* __restrict__ W1) {
    __shared__ __align__(16) uint32_t sxh[128 * 36];   // 18.4 KB
    __shared__ __align__(16) uint32_t swh[32 * 136];   // 17.4 KB
    int t = threadIdx.x;
    int r0 = blockIdx.x * 128;
    int w = t >> 5, l = t & 31;
    int mw = w & 1, nw = w >> 1;
    int g = l >> 2, tg = l & 3;
    float c[4][4][4];
    #pragma unroll
    for (int i = 0; i < 4; ++i)
        #pragma unroll
        for (int j = 0; j < 4; ++j)
            #pragma unroll
            for (int k = 0; k < 4; ++k) c[i][j][k] = 0.f;

    for (int kc = 0; kc < 8; ++kc) {
        int k0 = kc * 32;
        #pragma unroll
        for (int i = 0; i < 4; ++i) {           // x tile 128x32 via float4
            int e = t + i * 256;
            int row = e >> 3;
            int cq = (e & 7) * 4;
            int rr = min(r0 + row, N_NODES - 1);
            float4 xv = *(const float4*)&x[(size_t)rr * F_DIM + k0 + cq];
            float4 mv = *(const float4*)&g_mean[k0 + cq];
            float4 sv = *(const float4*)&g_rstd[k0 + cq];
            uint4 pv;
            pv.x = f2tf((xv.x - mv.x) * sv.x);
            pv.y = f2tf((xv.y - mv.y) * sv.y);
            pv.z = f2tf((xv.z - mv.z) * sv.z);
            pv.w = f2tf((xv.w - mv.w) * sv.w);
            *(uint4*)&sxh[row * 36 + cq] = pv;
        }
        #pragma unroll
        for (int i = 0; i < 4; ++i) {           // W tile 32x128 via float4
            int e = t + i * 256;
            int kk = e >> 5;
            int nq = (e & 31) * 4;
            float4 wv = *(const float4*)&W1[((size_t)(k0 + kk) * 64 + 63) * HID + nq];
            uint4 pv;
            pv.x = f2tf(wv.x); pv.y = f2tf(wv.y); pv.z = f2tf(wv.z); pv.w = f2tf(wv.w);
            *(uint4*)&swh[kk * 136 + nq] = pv;
        }
        __syncthreads();
        #pragma unroll
        for (int ks = 0; ks < 4; ++ks) {
            int kb = ks * 8;
            uint32_t ah[4][4];
            #pragma unroll
            for (int mt = 0; mt < 4; ++mt) {
                int mr = mw * 64 + mt * 16 + g;
                ah[mt][0] = sxh[mr * 36 + kb + tg];
                ah[mt][1] = sxh[(mr + 8) * 36 + kb + tg];
                ah[mt][2] = sxh[mr * 36 + kb + tg + 4];
                ah[mt][3] = sxh[(mr + 8) * 36 + kb + tg + 4];
            }
            #pragma unroll
            for (int nt = 0; nt < 4; ++nt) {
                int nc = nw * 32 + nt * 8 + g;
                uint32_t b0 = swh[(kb + tg) * 136 + nc];
                uint32_t b1 = swh[(kb + tg + 4) * 136 + nc];
                #pragma unroll
                for (int mt = 0; mt < 4; ++mt)
                    mma8(c[mt][nt], ah[mt][0], ah[mt][1], ah[mt][2], ah[mt][3], b0, b1);
            }
        }
        __syncthreads();
    }
    #pragma unroll
    for (int mt = 0; mt < 4; ++mt) {
        int row0 = r0 + mw * 64 + mt * 16 + g;
        float dv0 = (row0 < N_NODES) ? rsqrtf((float)(DEG(row0) + 1)) : 0.f;
        float dv1 = (row0 + 8 < N_NODES) ? rsqrtf((float)(DEG(row0 + 8) + 1)) : 0.f;
        #pragma unroll
        for (int nt = 0; nt < 4; ++nt) {
            int col = nw * 32 + nt * 8 + 2 * tg;
            float cc0 = g_c0[col], cc1 = g_c0[col + 1];
            if (row0 < N_NODES)
                g_g1h[(size_t)row0 * 64 + (col >> 1)] =
                    __floats2half2_rn((c[mt][nt][0] + cc0) * dv0, (c[mt][nt][1] + cc1) * dv0);
            if (row0 + 8 < N_NODES)
                g_g1h[(size_t)(row0 + 8) * 64 + (col >> 1)] =
                    __floats2half2_rn((c[mt][nt][2] + cc0) * dv1, (c[mt][nt][3] + cc1) * dv1);
        }
    }
}

// ===== K_E: conv1 aggregate + relu + gemm2, fused (one warp per node) =====
// launch_bounds(256,8): epilogue operands loaded AFTER the gather loop to keep loop regs <=32.
__global__ void __launch_bounds__(256, 8) kE(const float* __restrict__ b1,
                                             const float* __restrict__ W2) {
    __shared__ float sW2[HID * OUTC];           // [h][o], 3.5 KB
    int t = threadIdx.x, w = t >> 5, l = t & 31;
    for (int i = t; i < HID * OUTC; i += 256) sW2[i] = W2[i];
    __syncthreads();

    int n = blockIdx.x * 8 + w;                 // 2500 blocks x 8 warps
    int dg = DEG(n);
    int ne = min(dg, BKT);
    const int* bkt = g_csrc + n * BKT;

    int myidx = (l < ne) ? bkt[l] : 0;          // lane-parallel index prefetch

    float4 acc = make_float4(0.f, 0.f, 0.f, 0.f);
    {
        uint2 u = *(const uint2*)(g_g1h + (size_t)n * 64 + 2 * l);  // self (pre-scaled)
        float2 f0 = __half22float2(*(__half2*)&u.x);
        float2 f1 = __half22float2(*(__half2*)&u.y);
        acc.x += f0.x; acc.y += f0.y; acc.z += f1.x; acc.w += f1.y;
    }
    int nel = min(ne, 32);
    #pragma unroll 8
    for (int e = 0; e < nel; ++e) {
        int s = __shfl_sync(0xffffffffu, myidx, e);
        uint2 u = *(const uint2*)(g_g1h + (size_t)s * 64 + 2 * l);
        float2 f0 = __half22float2(*(__half2*)&u.x);
        float2 f1 = __half22float2(*(__half2*)&u.y);
        acc.x += f0.x; acc.y += f0.y; acc.z += f1.x; acc.w += f1.y;
    }
    for (int e = 32; e < ne; ++e) {             // rare tail (deg > 32)
        int s = bkt[e];
        uint2 u = *(const uint2*)(g_g1h + (size_t)s * 64 + 2 * l);
        float2 f0 = __half22float2(*(__half2*)&u.x);
        float2 f1 = __half22float2(*(__half2*)&u.y);
        acc.x += f0.x; acc.y += f0.y; acc.z += f1.x; acc.w += f1.y;
    }

    // epilogue (cold operands loaded here)
    float dn = rsqrtf((float)(dg + 1));
    float4 b1v = ((const float4*)b1)[l];
    float h0 = fmaxf(acc.x * dn + b1v.x, 0.f);
    float h1 = fmaxf(acc.y * dn + b1v.y, 0.f);
    float h2 = fmaxf(acc.z * dn + b1v.z, 0.f);
    float h3 = fmaxf(acc.w * dn + b1v.w, 0.f);
    const float* w0 = sW2 + (4 * l + 0) * OUTC;
    const float* w1 = sW2 + (4 * l + 1) * OUTC;
    const float* w2 = sW2 + (4 * l + 2) * OUTC;
    const float* w3 = sW2 + (4 * l + 3) * OUTC;
    float po[7];
    #pragma unroll
    for (int o = 0; o < 7; ++o)
        po[o] = h0 * w0[o] + h1 * w1[o] + h2 * w2[o] + h3 * w3[o];
    #pragma unroll
    for (int o = 0; o < 7; ++o)
        #pragma unroll
        for (int d2 = 16; d2 > 0; d2 >>= 1)
            po[o] += __shfl_xor_sync(0xffffffffu, po[o], d2);
    if (l == 0) {
        float4* gp = (float4*)(g_g2 + n * 8);
        gp[0] = make_float4(po[0] * dn, po[1] * dn, po[2] * dn, po[3] * dn);
        gp[1] = make_float4(po[4] * dn, po[5] * dn, po[6] * dn, 0.f);
    }
}

// ===== K_F: conv2 aggregate + bias + log_softmax (8-lane subgroup prefetch) =====
__global__ void __launch_bounds__(128) kF(const float* __restrict__ b2,
                                          float* __restrict__ out) {
    int t = threadIdx.x;
    int l = t & 31;
    int n = blockIdx.x * 16 + (t >> 3);
    int o = t & 7;
    unsigned gm = 0xFFu << (l & 24);            // this 8-lane group's mask
    int dg = DEG(n);
    int ne = min(dg, BKT);
    float dn = rsqrtf((float)(dg + 1));
    const int* bkt = g_csrc + n * BKT;

    int i0 = (o < ne)      ? bkt[o]      : 0;
    int i1 = (8 + o < ne)  ? bkt[8 + o]  : 0;
    int i2 = (16 + o < ne) ? bkt[16 + o] : 0;
    int i3 = (24 + o < ne) ? bkt[24 + o] : 0;

    float acc = g_g2[n * 8 + o];                // self (pre-scaled)
    int nel = min(ne, 32);
    int full = nel >> 3, rem = nel & 7;
    int pidx[4] = {i0, i1, i2, i3};
    #pragma unroll
    for (int p = 0; p < 4; ++p) {
        if (p < full) {
            #pragma unroll
            for (int k = 0; k < 8; ++k) {
                int s = __shfl_sync(gm, pidx[p], k, 8);
                acc += g_g2[s * 8 + o];
            }
        } else if (p == full) {
            for (int k = 0; k < rem; ++k) {
                int s = __shfl_sync(gm, pidx[p], k, 8);
                acc += g_g2[s * 8 + o];
            }
        }
    }
    for (int e = 32; e < ne; ++e)               // rare tail
        acc += g_g2[bkt[e] * 8 + o];

    float v = (o < OUTC) ? (acc * dn + b2[o]) : -3.0e38f;
    float m = v;
    #pragma unroll
    for (int d = 1; d < 8; d <<= 1) m = fmaxf(m, __shfl_xor_sync(0xffffffffu, m, d));
    float ex = (o < OUTC) ? expf(v - m) : 0.f;
    float s2 = ex;
    #pragma unroll
    for (int d = 1; d < 8; d <<= 1) s2 += __shfl_xor_sync(0xffffffffu, s2, d);
    if (o < OUTC) out[n * OUTC + o] = v - m - logf(s2);
}

// ---------------- launcher ----------------
extern "C" void kernel_launch(void* const* d_in, const int* in_sizes, int n_in,
                              void* d_out, int out_size) {
    const float* x   = (const float*)d_in[0];
    const float* emb = (const float*)d_in[1];
    const float* W1  = (const float*)d_in[2];
    const float* b1  = (const float*)d_in[3];
    const float* W2  = (const float*)d_in[4];
    const float* b2  = (const float*)d_in[5];
    const int*   ei  = (const int*)d_in[6];
    float* out = (float*)d_out;

    void* pm = nullptr;
    cudaGetSymbolAddress(&pm, g_meta);
    cudaMemsetAsync(pm, 0, (2 * N_NODES + 1) * sizeof(int));

    kA<<<SB + 64 + 157 + 313, 256>>>(x, emb, W1, ei);  // stats|c0|count|scatter + finalize tail
    kC<<<157, 256>>>(x, W1);                            // tf32 gemm1 (fp16 out)
    kE<<<2500, 256>>>(b1, W2);                          // agg1 + relu + gemm2
    kF<<<1250, 128>>>(b2, out);                         // agg2 + log_softmax
}

// round 17
// speedup vs baseline: 1.0792x; 1.0792x over previous
#include <cuda_runtime.h>
#include <cuda_fp16.h>
#include <math.h>
#include <stdint.h>

#define N_NODES 20000
#define F_DIM   256
#define HID     128
#define OUTC    7
#define E_EDGES 320000
#define SB      157      // stats blocks, 128 rows each
#define BKT     64       // neighbor bucket capacity per node

// ---------------- scratch ----------------
__device__ float   g_stat[SB][2][F_DIM];
__device__ float   g_mean[F_DIM];
__device__ float   g_rstd[F_DIM];
__device__ int     g_deg[N_NODES];               // in-edge count (self loop NOT included)
__device__ float   g_dinv[N_NODES];              // rsqrt(deg+1)
__device__ int     g_cur[N_NODES];
__device__ int     g_csrc[N_NODES * BKT];        // bucketed in-neighbors
__device__ float   g_c0p[64][2][HID];
__device__ float   g_c0[HID];
__device__ __half2 g_g1h[(size_t)N_NODES * 64];  // linear1 out (+c0), PRE-SCALED by dinv, fp16
__device__ float   g_g2[N_NODES * 8];            // linear2 out, PRE-SCALED by dinv

__device__ __forceinline__ uint32_t f2tf(float f) {
    uint32_t r; asm("cvt.rna.tf32.f32 %0, %1;" : "=r"(r) : "f"(f)); return r;
}
__device__ __forceinline__ void mma8(float* c, uint32_t a0, uint32_t a1, uint32_t a2,
                                     uint32_t a3, uint32_t b0, uint32_t b1) {
    asm volatile(
        "mma.sync.aligned.m16n8k8.row.col.f32.tf32.tf32.f32 "
        "{%0,%1,%2,%3},{%4,%5,%6,%7},{%8,%9},{%0,%1,%2,%3};"
        : "+f"(c[0]), "+f"(c[1]), "+f"(c[2]), "+f"(c[3])
        : "r"(a0), "r"(a1), "r"(a2), "r"(a3), "r"(b0), "r"(b1));
}

// ===== K_A: stats partials (157) | c0 partials (64) | count (157) | scatter (313) =====
__global__ void __launch_bounds__(256) kA(const float* __restrict__ x,
                                          const float* __restrict__ emb,
                                          const float* __restrict__ W1,
                                          const int* __restrict__ ei) {
    int b = blockIdx.x, t = threadIdx.x;
    if (b < SB) {
        int r0 = b * 128;
        float s = 0.f, q = 0.f;
        for (int r = 0; r < 128; ++r) {
            int rr = r0 + r;
            if (rr < N_NODES) {
                float v = x[(size_t)rr * F_DIM + t];
                s += v; q += v * v;
            }
        }
        g_stat[b][0][t] = s;
        g_stat[b][1][t] = q;
    } else if (b < SB + 64) {
        __shared__ float se[252];
        int cb = b - SB;
        int f0 = cb * 4;
        for (int i = t; i < 252; i += 256) se[i] = emb[f0 * 63 + i];
        __syncthreads();
        int h = t & 127, fp = t >> 7;
        float acc = 0.f;
        #pragma unroll
        for (int q2 = 0; q2 < 2; ++q2) {
            int f = f0 + fp * 2 + q2;
            const float* wrow = W1 + (size_t)f * 64 * HID + h;
            const float* ee = se + (fp * 2 + q2) * 63;
            #pragma unroll 7
            for (int j = 0; j < 63; ++j) acc += ee[j] * wrow[(size_t)j * HID];
        }
        g_c0p[cb][fp][h] = acc;
    } else if (b < SB + 64 + 157) {
        int base = ((b - SB - 64) * 256 + t) * 8;
        if (base < E_EDGES) {
            const int4* p = (const int4*)(ei + E_EDGES + base);
            int4 d0 = p[0], d1 = p[1];
            atomicAdd(&g_deg[d0.x], 1); atomicAdd(&g_deg[d0.y], 1);
            atomicAdd(&g_deg[d0.z], 1); atomicAdd(&g_deg[d0.w], 1);
            atomicAdd(&g_deg[d1.x], 1); atomicAdd(&g_deg[d1.y], 1);
            atomicAdd(&g_deg[d1.z], 1); atomicAdd(&g_deg[d1.w], 1);
        }
    } else {
        int base = ((b - SB - 64 - 157) * 256 + t) * 4;
        if (base < E_EDGES) {
            int4 s4 = *(const int4*)(ei + base);
            int4 d4 = *(const int4*)(ei + E_EDGES + base);
            int s[4] = {s4.x, s4.y, s4.z, s4.w};
            int d[4] = {d4.x, d4.y, d4.z, d4.w};
            int p[4];
            #pragma unroll
            for (int i = 0; i < 4; ++i) p[i] = atomicAdd(&g_cur[d[i]], 1);
            #pragma unroll
            for (int i = 0; i < 4; ++i)
                if (p[i] < BKT) g_csrc[d[i] * BKT + p[i]] = s[i];
        }
    }
}

// ===== K_B: finalize mean/rstd + c0 (block 0) | dinv (blocks 1..79) =====
__global__ void __launch_bounds__(256) kB() {
    int b = blockIdx.x, t = threadIdx.x;
    if (b == 0) {
        float s = 0.f, q = 0.f;
        for (int i = 0; i < SB; ++i) { s += g_stat[i][0][t]; q += g_stat[i][1][t]; }
        float m = s / N_NODES;
        float var = fmaxf(q / N_NODES - m * m, 0.f);
        float sd = sqrtf(var);
        if (sd == 0.f) sd = 1.f;
        g_mean[t] = m; g_rstd[t] = 1.f / sd;
        if (t < HID) {
            float c = 0.f;
            for (int i = 0; i < 64; ++i) c += g_c0p[i][0][t] + g_c0p[i][1][t];
            g_c0[t] = c;
        }
    } else {
        int i = (b - 1) * 256 + t;
        if (i < N_NODES) g_dinv[i] = rsqrtf((float)(g_deg[i] + 1));
    }
}

// ===== K_C: tf32 gemm1, 128-row tiles, float4 tile loads, fp16 dinv-scaled epilogue =====
__global__ void __launch_bounds__(256, 2) kC(const float* __restrict__ x,
                                             const float* __restrict__ W1) {
    __shared__ __align__(16) uint32_t sxh[128 * 36];   // 18.4 KB
    __shared__ __align__(16) uint32_t swh[32 * 136];   // 17.4 KB
    int t = threadIdx.x;
    int r0 = blockIdx.x * 128;
    int w = t >> 5, l = t & 31;
    int mw = w & 1, nw = w >> 1;
    int g = l >> 2, tg = l & 3;
    float c[4][4][4];
    #pragma unroll
    for (int i = 0; i < 4; ++i)
        #pragma unroll
        for (int j = 0; j < 4; ++j)
            #pragma unroll
            for (int k = 0; k < 4; ++k) c[i][j][k] = 0.f;

    for (int kc = 0; kc < 8; ++kc) {
        int k0 = kc * 32;
        #pragma unroll
        for (int i = 0; i < 4; ++i) {           // x tile 128x32 via float4
            int e = t + i * 256;
            int row = e >> 3;
            int cq = (e & 7) * 4;
            int rr = min(r0 + row, N_NODES - 1);
            float4 xv = *(const float4*)&x[(size_t)rr * F_DIM + k0 + cq];
            float4 mv = *(const float4*)&g_mean[k0 + cq];
            float4 sv = *(const float4*)&g_rstd[k0 + cq];
            uint4 pv;
            pv.x = f2tf((xv.x - mv.x) * sv.x);
            pv.y = f2tf((xv.y - mv.y) * sv.y);
            pv.z = f2tf((xv.z - mv.z) * sv.z);
            pv.w = f2tf((xv.w - mv.w) * sv.w);
            *(uint4*)&sxh[row * 36 + cq] = pv;
        }
        #pragma unroll
        for (int i = 0; i < 4; ++i) {           // W tile 32x128 via float4
            int e = t + i * 256;
            int kk = e >> 5;
            int nq = (e & 31) * 4;
            float4 wv = *(const float4*)&W1[((size_t)(k0 + kk) * 64 + 63) * HID + nq];
            uint4 pv;
            pv.x = f2tf(wv.x); pv.y = f2tf(wv.y); pv.z = f2tf(wv.z); pv.w = f2tf(wv.w);
            *(uint4*)&swh[kk * 136 + nq] = pv;
        }
        __syncthreads();
        #pragma unroll
        for (int ks = 0; ks < 4; ++ks) {
            int kb = ks * 8;
            uint32_t ah[4][4];
            #pragma unroll
            for (int mt = 0; mt < 4; ++mt) {
                int mr = mw * 64 + mt * 16 + g;
                ah[mt][0] = sxh[mr * 36 + kb + tg];
                ah[mt][1] = sxh[(mr + 8) * 36 + kb + tg];
                ah[mt][2] = sxh[mr * 36 + kb + tg + 4];
                ah[mt][3] = sxh[(mr + 8) * 36 + kb + tg + 4];
            }
            #pragma unroll
            for (int nt = 0; nt < 4; ++nt) {
                int nc = nw * 32 + nt * 8 + g;
                uint32_t b0 = swh[(kb + tg) * 136 + nc];
                uint32_t b1 = swh[(kb + tg + 4) * 136 + nc];
                #pragma unroll
                for (int mt = 0; mt < 4; ++mt)
                    mma8(c[mt][nt], ah[mt][0], ah[mt][1], ah[mt][2], ah[mt][3], b0, b1);
            }
        }
        __syncthreads();
    }
    #pragma unroll
    for (int mt = 0; mt < 4; ++mt) {
        int row0 = r0 + mw * 64 + mt * 16 + g;
        float dv0 = (row0 < N_NODES) ? g_dinv[row0] : 0.f;
        float dv1 = (row0 + 8 < N_NODES) ? g_dinv[row0 + 8] : 0.f;
        #pragma unroll
        for (int nt = 0; nt < 4; ++nt) {
            int col = nw * 32 + nt * 8 + 2 * tg;
            float cc0 = g_c0[col], cc1 = g_c0[col + 1];
            if (row0 < N_NODES)
                g_g1h[(size_t)row0 * 64 + (col >> 1)] =
                    __floats2half2_rn((c[mt][nt][0] + cc0) * dv0, (c[mt][nt][1] + cc1) * dv0);
            if (row0 + 8 < N_NODES)
                g_g1h[(size_t)(row0 + 8) * 64 + (col >> 1)] =
                    __floats2half2_rn((c[mt][nt][2] + cc0) * dv1, (c[mt][nt][3] + cc1) * dv1);
        }
    }
}

// ===== K_E: conv1 aggregate + relu + gemm2, fused (one warp per node) =====
__global__ void __launch_bounds__(256, 6) kE(const float* __restrict__ b1,
                                             const float* __restrict__ W2) {
    __shared__ float sW2[HID * OUTC];           // [h][o], 3.5 KB
    int t = threadIdx.x, w = t >> 5, l = t & 31;
    for (int i = t; i < HID * OUTC; i += 256) sW2[i] = W2[i];
    __syncthreads();

    int n = blockIdx.x * 8 + w;                 // 2500 blocks x 8 warps
    float4 b1v = ((const float4*)b1)[l];

    float dn = g_dinv[n];
    const int* bkt = g_csrc + n * BKT;
    int ne = min(g_deg[n], BKT);

    int myidx = (l < ne) ? bkt[l] : 0;          // lane-parallel index prefetch

    float4 acc = make_float4(0.f, 0.f, 0.f, 0.f);
    {
        uint2 u = *(const uint2*)(g_g1h + (size_t)n * 64 + 2 * l);  // self (pre-scaled)
        float2 f0 = __half22float2(*(__half2*)&u.x);
        float2 f1 = __half22float2(*(__half2*)&u.y);
        acc.x += f0.x; acc.y += f0.y; acc.z += f1.x; acc.w += f1.y;
    }
    int nel = min(ne, 32);
    #pragma unroll 8
    for (int e = 0; e < nel; ++e) {
        int s = __shfl_sync(0xffffffffu, myidx, e);
        uint2 u = *(const uint2*)(g_g1h + (size_t)s * 64 + 2 * l);
        float2 f0 = __half22float2(*(__half2*)&u.x);
        float2 f1 = __half22float2(*(__half2*)&u.y);
        acc.x += f0.x; acc.y += f0.y; acc.z += f1.x; acc.w += f1.y;
    }
    for (int e = 32; e < ne; ++e) {             // rare tail (deg > 32)
        int s = bkt[e];
        uint2 u = *(const uint2*)(g_g1h + (size_t)s * 64 + 2 * l);
        float2 f0 = __half22float2(*(__half2*)&u.x);
        float2 f1 = __half22float2(*(__half2*)&u.y);
        acc.x += f0.x; acc.y += f0.y; acc.z += f1.x; acc.w += f1.y;
    }

    float h0 = fmaxf(acc.x * dn + b1v.x, 0.f);
    float h1 = fmaxf(acc.y * dn + b1v.y, 0.f);
    float h2 = fmaxf(acc.z * dn + b1v.z, 0.f);
    float h3 = fmaxf(acc.w * dn + b1v.w, 0.f);
    const float* w0 = sW2 + (4 * l + 0) * OUTC;
    const float* w1 = sW2 + (4 * l + 1) * OUTC;
    const float* w2 = sW2 + (4 * l + 2) * OUTC;
    const float* w3 = sW2 + (4 * l + 3) * OUTC;
    float po[7];
    #pragma unroll
    for (int o = 0; o < 7; ++o)
        po[o] = h0 * w0[o] + h1 * w1[o] + h2 * w2[o] + h3 * w3[o];
    #pragma unroll
    for (int o = 0; o < 7; ++o)
        #pragma unroll
        for (int d2 = 16; d2 > 0; d2 >>= 1)
            po[o] += __shfl_xor_sync(0xffffffffu, po[o], d2);
    if (l == 0) {
        float4* gp = (float4*)(g_g2 + n * 8);
        gp[0] = make_float4(po[0] * dn, po[1] * dn, po[2] * dn, po[3] * dn);
        gp[1] = make_float4(po[4] * dn, po[5] * dn, po[6] * dn, 0.f);
    }
}

// ===== K_F: conv2 aggregate + bias + log_softmax (one WARP per node, 4 edge-slots x 8 outs) =====
__global__ void __launch_bounds__(256) kF(const float* __restrict__ b2,
                                          float* __restrict__ out) {
    int t = threadIdx.x, w = t >> 5, l = t & 31;
    int n = blockIdx.x * 8 + w;                 // 2500 blocks x 8 warps
    int j = l >> 3, o = l & 7;                  // edge-slot j=0..3, output o=0..7

    int ne = min(g_deg[n], BKT);
    float dn = g_dinv[n];
    const int* bkt = g_csrc + n * BKT;

    int myidx = (l < ne) ? bkt[l] : 0;          // lane-parallel index prefetch

    float acc = (j == 0) ? g_g2[n * 8 + o] : 0.f;   // self (pre-scaled)
    int nel = min(ne, 32);
    int kk = (nel + 3) >> 2;                    // uniform trip count across warp
    for (int k = 0; k < kk; ++k) {
        int e = k * 4 + j;
        int s = __shfl_sync(0xffffffffu, myidx, e & 31);
        if (e < nel) acc += g_g2[s * 8 + o];
    }
    for (int e = 32 + j; e < ne; e += 4)        // rare tail
        acc += g_g2[bkt[e] * 8 + o];

    // reduce across the 4 edge-slots (lanes o, o+8, o+16, o+24)
    acc += __shfl_xor_sync(0xffffffffu, acc, 8);
    acc += __shfl_xor_sync(0xffffffffu, acc, 16);

    float v = (o < OUTC) ? (acc * dn + b2[o]) : -3.0e38f;
    float m = v;
    #pragma unroll
    for (int d = 1; d < 8; d <<= 1) m = fmaxf(m, __shfl_xor_sync(0xffffffffu, m, d));
    float ex = (o < OUTC) ? expf(v - m) : 0.f;
    float s2 = ex;
    #pragma unroll
    for (int d = 1; d < 8; d <<= 1) s2 += __shfl_xor_sync(0xffffffffu, s2, d);
    if (j == 0 && o < OUTC) out[n * OUTC + o] = v - m - logf(s2);
}

// ---------------- launcher ----------------
extern "C" void kernel_launch(void* const* d_in, const int* in_sizes, int n_in,
                              void* d_out, int out_size) {
    const float* x   = (const float*)d_in[0];
    const float* emb = (const float*)d_in[1];
    const float* W1  = (const float*)d_in[2];
    const float* b1  = (const float*)d_in[3];
    const float* W2  = (const float*)d_in[4];
    const float* b2  = (const float*)d_in[5];
    const int*   ei  = (const int*)d_in[6];
    float* out = (float*)d_out;

    void *p_deg = nullptr, *p_cur = nullptr;
    cudaGetSymbolAddress(&p_deg, g_deg);
    cudaGetSymbolAddress(&p_cur, g_cur);
    cudaMemsetAsync(p_deg, 0, N_NODES * sizeof(int));
    cudaMemsetAsync(p_cur, 0, N_NODES * sizeof(int));

    kA<<<SB + 64 + 157 + 313, 256>>>(x, emb, W1, ei);  // stats | c0 | count | scatter
    kB<<<80, 256>>>();                                  // finalize stats+c0 | dinv
    kC<<<157, 256>>>(x, W1);                            // tf32 gemm1 (fp16 out)
    kE<<<2500, 256>>>(b1, W2);                          // agg1 + relu + gemm2
    kF<<<2500, 256>>>(b2, out);                         // agg2 + log_softmax (warp/node)
}